// round 6
// baseline (speedup 1.0000x reference)
#include <cuda_runtime.h>
#include <mma.h>
#include <cstdint>

using namespace nvcuda;

constexpr int B  = 4;
constexpr int S  = 2048;
constexpr int D  = 1024;
constexpr int H  = 16;
constexpr int DK = 64;
constexpr int M_TOK = B * S;          // 8192

// ---------------------------------------------------------------------------
// Device scratch
// ---------------------------------------------------------------------------
__device__ float    g_Q[(size_t)B * H * S * DK];        // [b,h,s,dk], pre-scaled 1/8, tf32-rounded
__device__ float    g_K[(size_t)B * H * S * DK];
__device__ float    g_V[(size_t)B * H * S * DK];
__device__ float    g_attn[(size_t)M_TOK * D];          // [b,s,h*dk], tf32-rounded
__device__ float    g_X[(size_t)M_TOK * D];             // tf32-rounded activations
__device__ float    g_W[(size_t)D * D];                 // tf32-rounded weights
__device__ unsigned g_maskbits[(size_t)B * S * S / 32];

// ---------------------------------------------------------------------------
// Mask packing
// ---------------------------------------------------------------------------
__global__ void pack_mask_kernel(const int* __restrict__ mask) {
    int idx = blockIdx.x * blockDim.x + threadIdx.x;
    int v = (mask[idx] != 0);
    unsigned bits = __ballot_sync(0xFFFFFFFFu, v);
    if ((threadIdx.x & 31) == 0) g_maskbits[idx >> 5] = bits;
}

// ---------------------------------------------------------------------------
// tf32 rounding prepass (RN), vectorized
// ---------------------------------------------------------------------------
__global__ void round_tf32_kernel(const float* __restrict__ in, float* __restrict__ out) {
    size_t i = (size_t)blockIdx.x * blockDim.x + threadIdx.x;
    float4 v = reinterpret_cast<const float4*>(in)[i];
    v.x = wmma::__float_to_tf32(v.x);
    v.y = wmma::__float_to_tf32(v.y);
    v.z = wmma::__float_to_tf32(v.z);
    v.w = wmma::__float_to_tf32(v.w);
    reinterpret_cast<float4*>(out)[i] = v;
}

// ---------------------------------------------------------------------------
// cp.async helpers
// ---------------------------------------------------------------------------
__device__ __forceinline__ void cp_async16(uint32_t dst, const void* src) {
    asm volatile("cp.async.cg.shared.global [%0], [%1], 16;" :: "r"(dst), "l"(src));
}
__device__ __forceinline__ void cp_commit() {
    asm volatile("cp.async.commit_group;");
}
__device__ __forceinline__ void cp_wait0() {
    asm volatile("cp.async.wait_group 0;" ::: "memory");
}

// ---------------------------------------------------------------------------
// TF32 WMMA GEMM, double-buffered cp.async: C = (X @ W^T + bias) * scale
//   X, W pre-rounded to tf32 -> NO in-loop conversions.
//   MODE 0: out[M,N] row-major (final output, NOT rounded)
//   MODE 1: out scattered to [b,h,s,dk], tf32-rounded
// Block 128x128x32, 256 thr, 8 warps (4x2), warp 32x64.
// ---------------------------------------------------------------------------
template <int MODE>
__global__ void __launch_bounds__(256, 2)
gemm_tf32(const float* __restrict__ X, const float* __restrict__ W,
          const float* __restrict__ bias, float* __restrict__ out, float scale)
{
    extern __shared__ float sm[];
    // buffer p: A at p*10240, B at p*10240 + 5120 (floats), stride 40
    const int t      = threadIdx.x;
    const int wid    = t >> 5;
    const int warp_m = wid >> 1;
    const int warp_n = wid & 1;
    const int m0     = blockIdx.y * 128;
    const int n0     = blockIdx.x * 128;

    const uint32_t smem_u32 = (uint32_t)__cvta_generic_to_shared(sm);

    auto stage = [&](int p, int k0) {
        uint32_t baseA = smem_u32 + (uint32_t)(p * 10240) * 4u;
        uint32_t baseB = baseA + 5120u * 4u;
#pragma unroll
        for (int j = 0; j < 4; ++j) {
            int idx = j * 256 + t;
            int r = idx >> 3, c4 = idx & 7;
            cp_async16(baseA + (uint32_t)(r * 40 + c4 * 4) * 4u,
                       X + (size_t)(m0 + r) * D + k0 + c4 * 4);
            cp_async16(baseB + (uint32_t)(r * 40 + c4 * 4) * 4u,
                       W + (size_t)(n0 + r) * D + k0 + c4 * 4);
        }
        cp_commit();
    };

    wmma::fragment<wmma::accumulator, 16, 16, 8, float> acc[2][4];
#pragma unroll
    for (int mt = 0; mt < 2; ++mt)
#pragma unroll
        for (int nt = 0; nt < 4; ++nt)
            wmma::fill_fragment(acc[mt][nt], 0.0f);

    stage(0, 0);

    for (int kt = 0; kt < 32; ++kt) {
        cp_wait0();
        __syncthreads();
        if (kt < 31) stage((kt + 1) & 1, (kt + 1) * 32);

        const float* As = sm + (kt & 1) * 10240;
        const float* Bs = As + 5120;
#pragma unroll
        for (int kk = 0; kk < 4; ++kk) {
            wmma::fragment<wmma::matrix_a, 16, 16, 8, wmma::precision::tf32, wmma::row_major> a[2];
#pragma unroll
            for (int mt = 0; mt < 2; ++mt)
                wmma::load_matrix_sync(a[mt], As + (warp_m * 32 + mt * 16) * 40 + kk * 8, 40);
#pragma unroll
            for (int nt = 0; nt < 4; ++nt) {
                wmma::fragment<wmma::matrix_b, 16, 16, 8, wmma::precision::tf32, wmma::col_major> b;
                wmma::load_matrix_sync(b, Bs + (warp_n * 64 + nt * 16) * 40 + kk * 8, 40);
#pragma unroll
                for (int mt = 0; mt < 2; ++mt)
                    wmma::mma_sync(acc[mt][nt], a[mt], b, acc[mt][nt]);
            }
        }
    }
    __syncthreads();

    // Epilogue: stage in shared [128][132]
    float* Cs = sm;
#pragma unroll
    for (int mt = 0; mt < 2; ++mt)
#pragma unroll
        for (int nt = 0; nt < 4; ++nt)
            wmma::store_matrix_sync(Cs + (warp_m * 32 + mt * 16) * 132 + warp_n * 64 + nt * 16,
                                    acc[mt][nt], 132, wmma::mem_row_major);
    __syncthreads();

    const int c  = t & 127;
    const int rh = t >> 7;
    const float bv = bias[n0 + c];
#pragma unroll 4
    for (int i = 0; i < 64; ++i) {
        int r = i * 2 + rh;
        float val = (Cs[r * 132 + c] + bv) * scale;
        if (MODE == 0) {
            out[(size_t)(m0 + r) * D + n0 + c] = val;
        } else {
            val = wmma::__float_to_tf32(val);
            int gm = m0 + r, gn = n0 + c;
            int bb = gm >> 11;
            int ss = gm & 2047;
            int hh = gn >> 6;
            int dd = gn & 63;
            out[(((size_t)bb * H + hh) * S + ss) * DK + dd] = val;
        }
    }
}

// ---------------------------------------------------------------------------
// Flash attention: block = (b, h, 128 q-rows). K-tiles of 64.
// Warp w owns q-rows [16w,16w+16): scores, softmax, P staging, O update are
// all warp-private -> only 2 block barriers per k-tile (K/V tile reuse).
// m/l/alpha live in registers. Inputs pre-rounded tf32.
// ---------------------------------------------------------------------------
__global__ void __launch_bounds__(256, 2)
flash_attn_kernel(const float* __restrict__ Q, const float* __restrict__ K,
                  const float* __restrict__ V, const unsigned* __restrict__ mb,
                  float* __restrict__ out)
{
    extern __shared__ float sm[];
    float* Ks = sm;            // [64][72]
    float* Vs = sm + 4608;     // [64][72]
    float* Ss = sm + 9216;     // [128][72]  Q init / scores / P / PV staging
    float* Os = sm + 18432;    // [128][72]

    const int t  = threadIdx.x;
    const int w  = t >> 5;
    const int h  = blockIdx.x;
    const int qt = blockIdx.y;
    const int b  = blockIdx.z;
    const int q0 = qt * 128;
    const size_t head = ((size_t)b * H + h) * S;

    const int r  = t >> 1;           // softmax / O row (warp-local: r in [16w,16w+16))
    const int c0 = (t & 1) * 32;

    // Load Q rows into Ss (warp-local rows), build a-fragments
    {
        const float4* src = reinterpret_cast<const float4*>(Q + (head + q0 + r) * DK + c0);
        float4* dst = reinterpret_cast<float4*>(Ss + r * 72 + c0);
#pragma unroll
        for (int j = 0; j < 8; ++j) dst[j] = src[j];
    }
    __syncwarp();
    wmma::fragment<wmma::matrix_a, 16, 16, 8, wmma::precision::tf32, wmma::row_major> qf[8];
#pragma unroll
    for (int kk = 0; kk < 8; ++kk)
        wmma::load_matrix_sync(qf[kk], Ss + (w * 16) * 72 + kk * 8, 72);

    // Init O (warp-local rows)
    {
        float4 z = make_float4(0.f, 0.f, 0.f, 0.f);
        float4* dst = reinterpret_cast<float4*>(Os + r * 72 + c0);
#pragma unroll
        for (int j = 0; j < 8; ++j) dst[j] = z;
    }
    float mrow = -1e30f, lrow = 0.0f;

    for (int kt = 0; kt < S / 64; ++kt) {
        __syncthreads();   // previous tile's Vs readers done; Ss qf loads done (kt=0)
        // Cooperative K,V tile load (64x64 each)
        const float* Kg = K + (head + kt * 64) * DK;
        const float* Vg = V + (head + kt * 64) * DK;
#pragma unroll
        for (int j = 0; j < 4; ++j) {
            int idx = j * 256 + t;
            int rr = idx >> 4, c4 = idx & 15;
            *reinterpret_cast<float4*>(Ks + rr * 72 + c4 * 4) =
                *reinterpret_cast<const float4*>(Kg + rr * DK + c4 * 4);
            *reinterpret_cast<float4*>(Vs + rr * 72 + c4 * 4) =
                *reinterpret_cast<const float4*>(Vg + rr * DK + c4 * 4);
        }
        __syncthreads();

        // S = Q @ K^T  (16x64 per warp)
        wmma::fragment<wmma::accumulator, 16, 16, 8, float> sacc[4];
#pragma unroll
        for (int nt = 0; nt < 4; ++nt) wmma::fill_fragment(sacc[nt], 0.0f);
#pragma unroll
        for (int kk = 0; kk < 8; ++kk) {
#pragma unroll
            for (int nt = 0; nt < 4; ++nt) {
                wmma::fragment<wmma::matrix_b, 16, 16, 8, wmma::precision::tf32, wmma::col_major> kb;
                wmma::load_matrix_sync(kb, Ks + (nt * 16) * 72 + kk * 8, 72);
                wmma::mma_sync(sacc[nt], qf[kk], kb, sacc[nt]);
            }
        }
#pragma unroll
        for (int nt = 0; nt < 4; ++nt)
            wmma::store_matrix_sync(Ss + (w * 16) * 72 + nt * 16, sacc[nt], 72, wmma::mem_row_major);
        __syncwarp();

        // Masked online softmax (thread: row r, 32 cols at c0)
        float* srow = Ss + r * 72 + c0;
        unsigned word = mb[(((size_t)(b * S + q0 + r)) * S + kt * 64 + c0) >> 5];
        float tmax = -1e30f;
#pragma unroll
        for (int j4 = 0; j4 < 8; ++j4) {
            float4 v = reinterpret_cast<float4*>(srow)[j4];
            v.x = ((word >> (j4 * 4 + 0)) & 1u) ? v.x : -1e9f;
            v.y = ((word >> (j4 * 4 + 1)) & 1u) ? v.y : -1e9f;
            v.z = ((word >> (j4 * 4 + 2)) & 1u) ? v.z : -1e9f;
            v.w = ((word >> (j4 * 4 + 3)) & 1u) ? v.w : -1e9f;
            tmax = fmaxf(tmax, fmaxf(fmaxf(v.x, v.y), fmaxf(v.z, v.w)));
            reinterpret_cast<float4*>(srow)[j4] = v;
        }
        tmax = fmaxf(tmax, __shfl_xor_sync(0xFFFFFFFFu, tmax, 1));
        float mnew  = fmaxf(mrow, tmax);
        float alpha = __expf(mrow - mnew);
        float rsum  = 0.0f;
#pragma unroll
        for (int j4 = 0; j4 < 8; ++j4) {
            float4 v = reinterpret_cast<float4*>(srow)[j4];
            v.x = __expf(v.x - mnew);
            v.y = __expf(v.y - mnew);
            v.z = __expf(v.z - mnew);
            v.w = __expf(v.w - mnew);
            rsum += (v.x + v.y) + (v.z + v.w);
            v.x = wmma::__float_to_tf32(v.x);
            v.y = wmma::__float_to_tf32(v.y);
            v.z = wmma::__float_to_tf32(v.z);
            v.w = wmma::__float_to_tf32(v.w);
            reinterpret_cast<float4*>(srow)[j4] = v;
        }
        rsum += __shfl_xor_sync(0xFFFFFFFFu, rsum, 1);
        mrow = mnew;
        lrow = lrow * alpha + rsum;
        __syncwarp();

        // PV = P @ V  (16x64 per warp)
        wmma::fragment<wmma::accumulator, 16, 16, 8, float> pacc[4];
#pragma unroll
        for (int nt = 0; nt < 4; ++nt) wmma::fill_fragment(pacc[nt], 0.0f);
#pragma unroll
        for (int kk = 0; kk < 8; ++kk) {
            wmma::fragment<wmma::matrix_a, 16, 16, 8, wmma::precision::tf32, wmma::row_major> pa;
            wmma::load_matrix_sync(pa, Ss + (w * 16) * 72 + kk * 8, 72);
#pragma unroll
            for (int nt = 0; nt < 4; ++nt) {
                wmma::fragment<wmma::matrix_b, 16, 16, 8, wmma::precision::tf32, wmma::row_major> vb;
                wmma::load_matrix_sync(vb, Vs + (kk * 8) * 72 + nt * 16, 72);
                wmma::mma_sync(pacc[nt], pa, vb, pacc[nt]);
            }
        }
        __syncwarp();
#pragma unroll
        for (int nt = 0; nt < 4; ++nt)
            wmma::store_matrix_sync(Ss + (w * 16) * 72 + nt * 16, pacc[nt], 72, wmma::mem_row_major);
        __syncwarp();

        // O = O*alpha + PV  (warp-local rows)
        {
            float4* Or = reinterpret_cast<float4*>(Os + r * 72 + c0);
            const float4* Pr = reinterpret_cast<const float4*>(Ss + r * 72 + c0);
#pragma unroll
            for (int j = 0; j < 8; ++j) {
                float4 o = Or[j], p = Pr[j];
                o.x = o.x * alpha + p.x;
                o.y = o.y * alpha + p.y;
                o.z = o.z * alpha + p.z;
                o.w = o.w * alpha + p.w;
                Or[j] = o;
            }
        }
    }

    // Epilogue: normalize, round to tf32 (feeds final GEMM), write [b,s,h*dk]
    float inv = 1.0f / lrow;
    float* og = out + ((size_t)(b * S + q0 + r)) * D + h * DK + c0;
    const float4* Or = reinterpret_cast<const float4*>(Os + r * 72 + c0);
#pragma unroll
    for (int j = 0; j < 8; ++j) {
        float4 o = Or[j];
        o.x = wmma::__float_to_tf32(o.x * inv);
        o.y = wmma::__float_to_tf32(o.y * inv);
        o.z = wmma::__float_to_tf32(o.z * inv);
        o.w = wmma::__float_to_tf32(o.w * inv);
        reinterpret_cast<float4*>(og)[j] = o;
    }
}

// ---------------------------------------------------------------------------
// Launch
// ---------------------------------------------------------------------------
extern "C" void kernel_launch(void* const* d_in, const int* in_sizes, int n_in,
                              void* d_out, int out_size)
{
    const float* query = (const float*)d_in[0];
    const float* key   = (const float*)d_in[1];
    const float* value = (const float*)d_in[2];
    const int*   mask  = (const int*)  d_in[3];
    const float* Wq    = (const float*)d_in[4];
    const float* bq    = (const float*)d_in[5];
    const float* Wk    = (const float*)d_in[6];
    const float* bk    = (const float*)d_in[7];
    const float* Wv    = (const float*)d_in[8];
    const float* bv    = (const float*)d_in[9];
    const float* Wo    = (const float*)d_in[10];
    const float* bo    = (const float*)d_in[11];
    float* out = (float*)d_out;

    float *pQ, *pK, *pV, *pA, *pX, *pW;
    unsigned* pMB;
    cudaGetSymbolAddress((void**)&pQ,  g_Q);
    cudaGetSymbolAddress((void**)&pK,  g_K);
    cudaGetSymbolAddress((void**)&pV,  g_V);
    cudaGetSymbolAddress((void**)&pA,  g_attn);
    cudaGetSymbolAddress((void**)&pX,  g_X);
    cudaGetSymbolAddress((void**)&pW,  g_W);
    cudaGetSymbolAddress((void**)&pMB, g_maskbits);

    const int gemm_smem = 2 * 10240 * 4;             // 81920 B (>= epilogue 67584)
    const int attn_smem = 27648 * 4;                 // 110592 B
    cudaFuncSetAttribute(gemm_tf32<0>, cudaFuncAttributeMaxDynamicSharedMemorySize, gemm_smem);
    cudaFuncSetAttribute(gemm_tf32<1>, cudaFuncAttributeMaxDynamicSharedMemorySize, gemm_smem);
    cudaFuncSetAttribute(flash_attn_kernel, cudaFuncAttributeMaxDynamicSharedMemorySize, attn_smem);

    const int rxb = (M_TOK * D / 4) / 256;   // activation rounding blocks
    const int rwb = (D * D / 4) / 256;       // weight rounding blocks
    dim3 gemm_grid(D / 128, M_TOK / 128);

    pack_mask_kernel<<<(B * S * S) / 256, 256>>>(mask);

    round_tf32_kernel<<<rxb, 256>>>(query, pX);
    round_tf32_kernel<<<rwb, 256>>>(Wq, pW);
    gemm_tf32<1><<<gemm_grid, 256, gemm_smem>>>(pX, pW, bq, pQ, 0.125f);

    round_tf32_kernel<<<rxb, 256>>>(key, pX);
    round_tf32_kernel<<<rwb, 256>>>(Wk, pW);
    gemm_tf32<1><<<gemm_grid, 256, gemm_smem>>>(pX, pW, bk, pK, 1.0f);

    round_tf32_kernel<<<rxb, 256>>>(value, pX);
    round_tf32_kernel<<<rwb, 256>>>(Wv, pW);
    gemm_tf32<1><<<gemm_grid, 256, gemm_smem>>>(pX, pW, bv, pV, 1.0f);

    dim3 attn_grid(H, S / 128, B);
    flash_attn_kernel<<<attn_grid, 256, attn_smem>>>(pQ, pK, pV, pMB, pA);

    round_tf32_kernel<<<rwb, 256>>>(Wo, pW);
    gemm_tf32<0><<<gemm_grid, 256, gemm_smem>>>(pA, pW, bo, out, 1.0f);
}

// round 8
// speedup vs baseline: 1.0019x; 1.0019x over previous
#include <cuda_runtime.h>
#include <mma.h>
#include <cstdint>

using namespace nvcuda;

constexpr int B  = 4;
constexpr int S  = 2048;
constexpr int D  = 1024;
constexpr int H  = 16;
constexpr int DK = 64;
constexpr int M_TOK = B * S;          // 8192

// ---------------------------------------------------------------------------
// Device scratch
// ---------------------------------------------------------------------------
__device__ float    g_Q[(size_t)B * H * S * DK];        // [b,h,s,dk], pre-scaled 1/8, tf32-rounded
__device__ float    g_K[(size_t)B * H * S * DK];
__device__ float    g_V[(size_t)B * H * S * DK];
__device__ float    g_attn[(size_t)M_TOK * D];          // [b,s,h*dk], tf32-rounded
__device__ float    g_X[(size_t)M_TOK * D];             // tf32-rounded activations
__device__ float    g_W[(size_t)D * D];                 // tf32-rounded weights
__device__ unsigned g_maskbits[(size_t)B * S * S / 32];

// ---------------------------------------------------------------------------
// Mask packing
// ---------------------------------------------------------------------------
__global__ void pack_mask_kernel(const int* __restrict__ mask) {
    int idx = blockIdx.x * blockDim.x + threadIdx.x;
    int v = (mask[idx] != 0);
    unsigned bits = __ballot_sync(0xFFFFFFFFu, v);
    if ((threadIdx.x & 31) == 0) g_maskbits[idx >> 5] = bits;
}

// ---------------------------------------------------------------------------
// tf32 rounding prepass (RN), vectorized
// ---------------------------------------------------------------------------
__global__ void round_tf32_kernel(const float* __restrict__ in, float* __restrict__ out) {
    size_t i = (size_t)blockIdx.x * blockDim.x + threadIdx.x;
    float4 v = reinterpret_cast<const float4*>(in)[i];
    v.x = wmma::__float_to_tf32(v.x);
    v.y = wmma::__float_to_tf32(v.y);
    v.z = wmma::__float_to_tf32(v.z);
    v.w = wmma::__float_to_tf32(v.w);
    reinterpret_cast<float4*>(out)[i] = v;
}

// ---------------------------------------------------------------------------
// cp.async helpers
// ---------------------------------------------------------------------------
__device__ __forceinline__ void cp_async16(uint32_t dst, const void* src) {
    asm volatile("cp.async.cg.shared.global [%0], [%1], 16;" :: "r"(dst), "l"(src));
}
__device__ __forceinline__ void cp_commit() {
    asm volatile("cp.async.commit_group;");
}
__device__ __forceinline__ void cp_wait0() {
    asm volatile("cp.async.wait_group 0;" ::: "memory");
}

// ---------------------------------------------------------------------------
// TF32 WMMA GEMM, double-buffered cp.async: C = (X @ W^T + bias) * scale
//   X, W pre-rounded to tf32 -> NO in-loop conversions.
//   MODE 0: out[M,N] row-major (final output, NOT rounded)
//   MODE 1: out scattered to [b,h,s,dk], tf32-rounded
// Block 128x128x32, 256 thr, 8 warps (4x2), warp 32x64.
// ---------------------------------------------------------------------------
template <int MODE>
__global__ void __launch_bounds__(256, 2)
gemm_tf32(const float* __restrict__ X, const float* __restrict__ W,
          const float* __restrict__ bias, float* __restrict__ out, float scale)
{
    extern __shared__ float sm[];
    // buffer p: A at p*10240, B at p*10240 + 5120 (floats), stride 40
    const int t      = threadIdx.x;
    const int wid    = t >> 5;
    const int warp_m = wid >> 1;
    const int warp_n = wid & 1;
    const int m0     = blockIdx.y * 128;
    const int n0     = blockIdx.x * 128;

    const uint32_t smem_u32 = (uint32_t)__cvta_generic_to_shared(sm);

    auto stage = [&](int p, int k0) {
        uint32_t baseA = smem_u32 + (uint32_t)(p * 10240) * 4u;
        uint32_t baseB = baseA + 5120u * 4u;
#pragma unroll
        for (int j = 0; j < 4; ++j) {
            int idx = j * 256 + t;
            int r = idx >> 3, c4 = idx & 7;
            cp_async16(baseA + (uint32_t)(r * 40 + c4 * 4) * 4u,
                       X + (size_t)(m0 + r) * D + k0 + c4 * 4);
            cp_async16(baseB + (uint32_t)(r * 40 + c4 * 4) * 4u,
                       W + (size_t)(n0 + r) * D + k0 + c4 * 4);
        }
        cp_commit();
    };

    wmma::fragment<wmma::accumulator, 16, 16, 8, float> acc[2][4];
#pragma unroll
    for (int mt = 0; mt < 2; ++mt)
#pragma unroll
        for (int nt = 0; nt < 4; ++nt)
            wmma::fill_fragment(acc[mt][nt], 0.0f);

    stage(0, 0);

    for (int kt = 0; kt < 32; ++kt) {
        cp_wait0();
        __syncthreads();
        if (kt < 31) stage((kt + 1) & 1, (kt + 1) * 32);

        const float* As = sm + (kt & 1) * 10240;
        const float* Bs = As + 5120;
#pragma unroll
        for (int kk = 0; kk < 4; ++kk) {
            wmma::fragment<wmma::matrix_a, 16, 16, 8, wmma::precision::tf32, wmma::row_major> a[2];
#pragma unroll
            for (int mt = 0; mt < 2; ++mt)
                wmma::load_matrix_sync(a[mt], As + (warp_m * 32 + mt * 16) * 40 + kk * 8, 40);
#pragma unroll
            for (int nt = 0; nt < 4; ++nt) {
                wmma::fragment<wmma::matrix_b, 16, 16, 8, wmma::precision::tf32, wmma::col_major> b;
                wmma::load_matrix_sync(b, Bs + (warp_n * 64 + nt * 16) * 40 + kk * 8, 40);
#pragma unroll
                for (int mt = 0; mt < 2; ++mt)
                    wmma::mma_sync(acc[mt][nt], a[mt], b, acc[mt][nt]);
            }
        }
    }
    __syncthreads();

    // Epilogue: stage in shared [128][132]
    float* Cs = sm;
#pragma unroll
    for (int mt = 0; mt < 2; ++mt)
#pragma unroll
        for (int nt = 0; nt < 4; ++nt)
            wmma::store_matrix_sync(Cs + (warp_m * 32 + mt * 16) * 132 + warp_n * 64 + nt * 16,
                                    acc[mt][nt], 132, wmma::mem_row_major);
    __syncthreads();

    const int c  = t & 127;
    const int rh = t >> 7;
    const float bv = bias[n0 + c];
#pragma unroll 4
    for (int i = 0; i < 64; ++i) {
        int r = i * 2 + rh;
        float val = (Cs[r * 132 + c] + bv) * scale;
        if (MODE == 0) {
            out[(size_t)(m0 + r) * D + n0 + c] = val;
        } else {
            val = wmma::__float_to_tf32(val);
            int gm = m0 + r, gn = n0 + c;
            int bb = gm >> 11;
            int ss = gm & 2047;
            int hh = gn >> 6;
            int dd = gn & 63;
            out[(((size_t)bb * H + hh) * S + ss) * DK + dd] = val;
        }
    }
}

// ---------------------------------------------------------------------------
// Flash attention: block = (b, h, 128 q-rows). K-tiles of 64.
// Warp w owns q-rows [16w,16w+16): scores, softmax, P staging, O update are
// all warp-private -> only 2 block barriers per k-tile (K/V tile reuse).
// m/l/alpha live in registers. Inputs pre-rounded tf32.
// ---------------------------------------------------------------------------
__global__ void __launch_bounds__(256, 2)
flash_attn_kernel(const float* __restrict__ Q, const float* __restrict__ K,
                  const float* __restrict__ V, const unsigned* __restrict__ mb,
                  float* __restrict__ out)
{
    extern __shared__ float sm[];
    float* Ks = sm;            // [64][72]
    float* Vs = sm + 4608;     // [64][72]
    float* Ss = sm + 9216;     // [128][72]  Q init / scores / P / PV staging
    float* Os = sm + 18432;    // [128][72]

    const int t  = threadIdx.x;
    const int w  = t >> 5;
    const int h  = blockIdx.x;
    const int qt = blockIdx.y;
    const int b  = blockIdx.z;
    const int q0 = qt * 128;
    const size_t head = ((size_t)b * H + h) * S;

    const int r  = t >> 1;           // softmax / O row (warp-local: r in [16w,16w+16))
    const int c0 = (t & 1) * 32;

    // Load Q rows into Ss (warp-local rows), build a-fragments
    {
        const float4* src = reinterpret_cast<const float4*>(Q + (head + q0 + r) * DK + c0);
        float4* dst = reinterpret_cast<float4*>(Ss + r * 72 + c0);
#pragma unroll
        for (int j = 0; j < 8; ++j) dst[j] = src[j];
    }
    __syncwarp();
    wmma::fragment<wmma::matrix_a, 16, 16, 8, wmma::precision::tf32, wmma::row_major> qf[8];
#pragma unroll
    for (int kk = 0; kk < 8; ++kk)
        wmma::load_matrix_sync(qf[kk], Ss + (w * 16) * 72 + kk * 8, 72);

    // Init O (warp-local rows)
    {
        float4 z = make_float4(0.f, 0.f, 0.f, 0.f);
        float4* dst = reinterpret_cast<float4*>(Os + r * 72 + c0);
#pragma unroll
        for (int j = 0; j < 8; ++j) dst[j] = z;
    }
    float mrow = -1e30f, lrow = 0.0f;

    for (int kt = 0; kt < S / 64; ++kt) {
        __syncthreads();   // previous tile's Vs readers done; Ss qf loads done (kt=0)
        // Cooperative K,V tile load (64x64 each)
        const float* Kg = K + (head + kt * 64) * DK;
        const float* Vg = V + (head + kt * 64) * DK;
#pragma unroll
        for (int j = 0; j < 4; ++j) {
            int idx = j * 256 + t;
            int rr = idx >> 4, c4 = idx & 15;
            *reinterpret_cast<float4*>(Ks + rr * 72 + c4 * 4) =
                *reinterpret_cast<const float4*>(Kg + rr * DK + c4 * 4);
            *reinterpret_cast<float4*>(Vs + rr * 72 + c4 * 4) =
                *reinterpret_cast<const float4*>(Vg + rr * DK + c4 * 4);
        }
        __syncthreads();

        // S = Q @ K^T  (16x64 per warp)
        wmma::fragment<wmma::accumulator, 16, 16, 8, float> sacc[4];
#pragma unroll
        for (int nt = 0; nt < 4; ++nt) wmma::fill_fragment(sacc[nt], 0.0f);
#pragma unroll
        for (int kk = 0; kk < 8; ++kk) {
#pragma unroll
            for (int nt = 0; nt < 4; ++nt) {
                wmma::fragment<wmma::matrix_b, 16, 16, 8, wmma::precision::tf32, wmma::col_major> kb;
                wmma::load_matrix_sync(kb, Ks + (nt * 16) * 72 + kk * 8, 72);
                wmma::mma_sync(sacc[nt], qf[kk], kb, sacc[nt]);
            }
        }
#pragma unroll
        for (int nt = 0; nt < 4; ++nt)
            wmma::store_matrix_sync(Ss + (w * 16) * 72 + nt * 16, sacc[nt], 72, wmma::mem_row_major);
        __syncwarp();

        // Masked online softmax (thread: row r, 32 cols at c0)
        float* srow = Ss + r * 72 + c0;
        unsigned word = mb[(((size_t)(b * S + q0 + r)) * S + kt * 64 + c0) >> 5];
        float tmax = -1e30f;
#pragma unroll
        for (int j4 = 0; j4 < 8; ++j4) {
            float4 v = reinterpret_cast<float4*>(srow)[j4];
            v.x = ((word >> (j4 * 4 + 0)) & 1u) ? v.x : -1e9f;
            v.y = ((word >> (j4 * 4 + 1)) & 1u) ? v.y : -1e9f;
            v.z = ((word >> (j4 * 4 + 2)) & 1u) ? v.z : -1e9f;
            v.w = ((word >> (j4 * 4 + 3)) & 1u) ? v.w : -1e9f;
            tmax = fmaxf(tmax, fmaxf(fmaxf(v.x, v.y), fmaxf(v.z, v.w)));
            reinterpret_cast<float4*>(srow)[j4] = v;
        }
        tmax = fmaxf(tmax, __shfl_xor_sync(0xFFFFFFFFu, tmax, 1));
        float mnew  = fmaxf(mrow, tmax);
        float alpha = __expf(mrow - mnew);
        float rsum  = 0.0f;
#pragma unroll
        for (int j4 = 0; j4 < 8; ++j4) {
            float4 v = reinterpret_cast<float4*>(srow)[j4];
            v.x = __expf(v.x - mnew);
            v.y = __expf(v.y - mnew);
            v.z = __expf(v.z - mnew);
            v.w = __expf(v.w - mnew);
            rsum += (v.x + v.y) + (v.z + v.w);
            v.x = wmma::__float_to_tf32(v.x);
            v.y = wmma::__float_to_tf32(v.y);
            v.z = wmma::__float_to_tf32(v.z);
            v.w = wmma::__float_to_tf32(v.w);
            reinterpret_cast<float4*>(srow)[j4] = v;
        }
        rsum += __shfl_xor_sync(0xFFFFFFFFu, rsum, 1);
        mrow = mnew;
        lrow = lrow * alpha + rsum;
        __syncwarp();

        // PV = P @ V  (16x64 per warp)
        wmma::fragment<wmma::accumulator, 16, 16, 8, float> pacc[4];
#pragma unroll
        for (int nt = 0; nt < 4; ++nt) wmma::fill_fragment(pacc[nt], 0.0f);
#pragma unroll
        for (int kk = 0; kk < 8; ++kk) {
            wmma::fragment<wmma::matrix_a, 16, 16, 8, wmma::precision::tf32, wmma::row_major> pa;
            wmma::load_matrix_sync(pa, Ss + (w * 16) * 72 + kk * 8, 72);
#pragma unroll
            for (int nt = 0; nt < 4; ++nt) {
                wmma::fragment<wmma::matrix_b, 16, 16, 8, wmma::precision::tf32, wmma::row_major> vb;
                wmma::load_matrix_sync(vb, Vs + (kk * 8) * 72 + nt * 16, 72);
                wmma::mma_sync(pacc[nt], pa, vb, pacc[nt]);
            }
        }
        __syncwarp();
#pragma unroll
        for (int nt = 0; nt < 4; ++nt)
            wmma::store_matrix_sync(Ss + (w * 16) * 72 + nt * 16, pacc[nt], 72, wmma::mem_row_major);
        __syncwarp();

        // O = O*alpha + PV  (warp-local rows)
        {
            float4* Or = reinterpret_cast<float4*>(Os + r * 72 + c0);
            const float4* Pr = reinterpret_cast<const float4*>(Ss + r * 72 + c0);
#pragma unroll
            for (int j = 0; j < 8; ++j) {
                float4 o = Or[j], p = Pr[j];
                o.x = o.x * alpha + p.x;
                o.y = o.y * alpha + p.y;
                o.z = o.z * alpha + p.z;
                o.w = o.w * alpha + p.w;
                Or[j] = o;
            }
        }
    }

    // Epilogue: normalize, round to tf32 (feeds final GEMM), write [b,s,h*dk]
    float inv = 1.0f / lrow;
    float* og = out + ((size_t)(b * S + q0 + r)) * D + h * DK + c0;
    const float4* Or = reinterpret_cast<const float4*>(Os + r * 72 + c0);
#pragma unroll
    for (int j = 0; j < 8; ++j) {
        float4 o = Or[j];
        o.x = wmma::__float_to_tf32(o.x * inv);
        o.y = wmma::__float_to_tf32(o.y * inv);
        o.z = wmma::__float_to_tf32(o.z * inv);
        o.w = wmma::__float_to_tf32(o.w * inv);
        reinterpret_cast<float4*>(og)[j] = o;
    }
}

// ---------------------------------------------------------------------------
// Launch
// ---------------------------------------------------------------------------
extern "C" void kernel_launch(void* const* d_in, const int* in_sizes, int n_in,
                              void* d_out, int out_size)
{
    const float* query = (const float*)d_in[0];
    const float* key   = (const float*)d_in[1];
    const float* value = (const float*)d_in[2];
    const int*   mask  = (const int*)  d_in[3];
    const float* Wq    = (const float*)d_in[4];
    const float* bq    = (const float*)d_in[5];
    const float* Wk    = (const float*)d_in[6];
    const float* bk    = (const float*)d_in[7];
    const float* Wv    = (const float*)d_in[8];
    const float* bv    = (const float*)d_in[9];
    const float* Wo    = (const float*)d_in[10];
    const float* bo    = (const float*)d_in[11];
    float* out = (float*)d_out;

    float *pQ, *pK, *pV, *pA, *pX, *pW;
    unsigned* pMB;
    cudaGetSymbolAddress((void**)&pQ,  g_Q);
    cudaGetSymbolAddress((void**)&pK,  g_K);
    cudaGetSymbolAddress((void**)&pV,  g_V);
    cudaGetSymbolAddress((void**)&pA,  g_attn);
    cudaGetSymbolAddress((void**)&pX,  g_X);
    cudaGetSymbolAddress((void**)&pW,  g_W);
    cudaGetSymbolAddress((void**)&pMB, g_maskbits);

    const int gemm_smem = 2 * 10240 * 4;             // 81920 B (>= epilogue 67584)
    const int attn_smem = 27648 * 4;                 // 110592 B
    cudaFuncSetAttribute(gemm_tf32<0>, cudaFuncAttributeMaxDynamicSharedMemorySize, gemm_smem);
    cudaFuncSetAttribute(gemm_tf32<1>, cudaFuncAttributeMaxDynamicSharedMemorySize, gemm_smem);
    cudaFuncSetAttribute(flash_attn_kernel, cudaFuncAttributeMaxDynamicSharedMemorySize, attn_smem);

    const int rxb = (M_TOK * D / 4) / 256;   // activation rounding blocks
    const int rwb = (D * D / 4) / 256;       // weight rounding blocks
    dim3 gemm_grid(D / 128, M_TOK / 128);

    pack_mask_kernel<<<(B * S * S) / 256, 256>>>(mask);

    round_tf32_kernel<<<rxb, 256>>>(query, pX);
    round_tf32_kernel<<<rwb, 256>>>(Wq, pW);
    gemm_tf32<1><<<gemm_grid, 256, gemm_smem>>>(pX, pW, bq, pQ, 0.125f);

    round_tf32_kernel<<<rxb, 256>>>(key, pX);
    round_tf32_kernel<<<rwb, 256>>>(Wk, pW);
    gemm_tf32<1><<<gemm_grid, 256, gemm_smem>>>(pX, pW, bk, pK, 1.0f);

    round_tf32_kernel<<<rxb, 256>>>(value, pX);
    round_tf32_kernel<<<rwb, 256>>>(Wv, pW);
    gemm_tf32<1><<<gemm_grid, 256, gemm_smem>>>(pX, pW, bv, pV, 1.0f);

    dim3 attn_grid(H, S / 128, B);
    flash_attn_kernel<<<attn_grid, 256, attn_smem>>>(pQ, pK, pV, pMB, pA);

    round_tf32_kernel<<<rwb, 256>>>(Wo, pW);
    gemm_tf32<0><<<gemm_grid, 256, gemm_smem>>>(pA, pW, bo, out, 1.0f);
}